// round 12
// baseline (speedup 1.0000x reference)
#include <cuda_runtime.h>
#include <cuda_bf16.h>
#include <cuda_fp16.h>
#include <cstdint>

// Problem constants
#define BB 2
#define CC 256
#define NN 4096          // 64*64
#define DD 768           // 3*CC
#define IN 32            // inter

// Flash tiling (proven geometry, 512 threads)
#define TMQ 128          // q rows per block
#define TNK 256          // keys per j-tile
#define KC 64            // feature chunk (=128B bf16 row)
#define NCH (DD / KC)    // 12
#define SPLITS 2
#define KEYS (NN / SPLITS)   // 2048
#define NJT (KEYS / TNK)     // 8
#define NTHR 512

// SMEM layout (bytes) for flash
#define KOFF   16384
#define STAGE_BYTES 49152      // Q 16K + K 32K
#define VTS_OFF 98304          // fp16 VT [32][272] (pitch 544B)
#define VT_PITCH 544
#define PM_OFF   115712        // fp32 [2][128]
#define PSUM_OFF 116736        // fp32 [2][128]
#define MR_OFF   117760        // fp32 [128]
#define LR_OFF   118272
#define SCR_OFF  118784
#define FLASH_SMEM 119296

// Scratch (static device globals; no allocation)
__device__ float d_M[BB][2 * CC][NN];                     // pooled variants 3,5 (fp32)
__device__ __align__(16) __nv_bfloat16 d_Mt[BB][NN][DD];  // token-major, scaled, bf16
__device__ __align__(16) __half d_GXT[BB][IN][NN];        // g_x as [b][i][n], fp16
__device__ float d_S[3][BB][CC];
__device__ float d_sqrtV[BB][3];
__device__ float d_part[BB * SPLITS][NN][IN];             // split partial O (unnormalized)
__device__ float2 d_ml[BB * SPLITS][NN];                  // split (m, l)

// ---------------- helpers ----------------
__device__ __forceinline__ uint32_t smem_u32(const void* p) {
    uint32_t a;
    asm("{ .reg .u64 t; cvta.to.shared.u64 t, %1; cvt.u32.u64 %0, t; }" : "=r"(a) : "l"(p));
    return a;
}
__device__ __forceinline__ uint32_t sw128(uint32_t bo) { return bo ^ ((bo >> 3) & 0x70); }

__device__ __forceinline__ void cpa16(uint32_t dst, const void* src) {
    asm volatile("cp.async.cg.shared.global [%0], [%1], 16;" :: "r"(dst), "l"(src));
}
__device__ __forceinline__ void cp_commit() { asm volatile("cp.async.commit_group;"); }
__device__ __forceinline__ void cp_wait0() { asm volatile("cp.async.wait_group 0;"); }
__device__ __forceinline__ void cp_wait1() { asm volatile("cp.async.wait_group 1;"); }

__device__ __forceinline__ void ldsm4(uint32_t* r, uint32_t addr) {
    asm volatile("ldmatrix.sync.aligned.m8n8.x4.shared.b16 {%0,%1,%2,%3}, [%4];"
                 : "=r"(r[0]), "=r"(r[1]), "=r"(r[2]), "=r"(r[3]) : "r"(addr));
}
__device__ __forceinline__ void mma_bf16(float* c, const uint32_t* a, uint32_t b0, uint32_t b1) {
    asm volatile("mma.sync.aligned.m16n8k16.row.col.f32.bf16.bf16.f32 "
                 "{%0,%1,%2,%3},{%4,%5,%6,%7},{%8,%9},{%0,%1,%2,%3};"
                 : "+f"(c[0]), "+f"(c[1]), "+f"(c[2]), "+f"(c[3])
                 : "r"(a[0]), "r"(a[1]), "r"(a[2]), "r"(a[3]), "r"(b0), "r"(b1));
}
__device__ __forceinline__ void mma_f16(float* c, const uint32_t* a, uint32_t b0, uint32_t b1) {
    asm volatile("mma.sync.aligned.m16n8k16.row.col.f32.f16.f16.f32 "
                 "{%0,%1,%2,%3},{%4,%5,%6,%7},{%8,%9},{%0,%1,%2,%3};"
                 : "+f"(c[0]), "+f"(c[1]), "+f"(c[2]), "+f"(c[3])
                 : "r"(a[0]), "r"(a[1]), "r"(a[2]), "r"(a[3]), "r"(b0), "r"(b1));
}
__device__ __forceinline__ float qredmax(float v) {
    v = fmaxf(v, __shfl_xor_sync(0xffffffffu, v, 1));
    v = fmaxf(v, __shfl_xor_sync(0xffffffffu, v, 2));
    return v;
}
__device__ __forceinline__ float qredsum(float v) {
    v += __shfl_xor_sync(0xffffffffu, v, 1);
    v += __shfl_xor_sync(0xffffffffu, v, 2);
    return v;
}

// ---------------- kernel 1: MERGED pool + gx (R10-proven) ----------------
__global__ __launch_bounds__(256) void prep_kernel(const float* __restrict__ x,
                                                   const float* __restrict__ Wg) {
    __shared__ __align__(16) char smraw[49152];
    const int bid = blockIdx.x;
    const int t = threadIdx.x;

    if (bid < 512) {
        const int c = bid & 255, b = bid >> 8;
        const float* xp = x + ((size_t)(b * CC + c)) * NN;
        float (*xs)[64] = (float (*)[64])smraw;
        float (*h3)[64] = (float (*)[64])(smraw + 16384);
        float (*h5)[64] = (float (*)[64])(smraw + 32768);

        for (int p = t; p < NN; p += 256) xs[p >> 6][p & 63] = xp[p];
        __syncthreads();
        for (int p = t; p < NN; p += 256) {
            int h = p >> 6, w = p & 63;
            float c0 = xs[h][w];
            float l1 = (w > 0)  ? xs[h][w - 1] : 0.f;
            float r1 = (w < 63) ? xs[h][w + 1] : 0.f;
            float l2 = (w > 1)  ? xs[h][w - 2] : 0.f;
            float r2 = (w < 62) ? xs[h][w + 2] : 0.f;
            h3[h][w] = l1 + c0 + r1;
            h5[h][w] = l2 + l1 + c0 + r1 + r2;
        }
        __syncthreads();
        float s1 = 0.f, s3 = 0.f, s5 = 0.f;
        float* M3 = &d_M[b][c][0];
        float* M5 = &d_M[b][CC + c][0];
        for (int p = t; p < NN; p += 256) {
            int h = p >> 6, w = p & 63;
            float v0 = xs[h][w];
            float u1 = (h > 0)  ? h3[h - 1][w] : 0.f;
            float dn1 = (h < 63) ? h3[h + 1][w] : 0.f;
            float u2 = (h > 1)  ? h5[h - 2][w] : 0.f;
            float dn2 = (h < 62) ? h5[h + 2][w] : 0.f;
            float u1b = (h > 0)  ? h5[h - 1][w] : 0.f;
            float dn1b = (h < 63) ? h5[h + 1][w] : 0.f;
            float p3 = (u1 + h3[h][w] + dn1) * (1.f / 9.f);
            float p5 = (u2 + u1b + h5[h][w] + dn1b + dn2) * (1.f / 25.f);
            M3[p] = p3; M5[p] = p5;
            s1 += v0; s3 += p3; s5 += p5;
        }
        __syncthreads();
        float* r1 = (float*)smraw;
        float* r3 = (float*)(smraw + 16384);
        float* r5 = (float*)(smraw + 32768);
        r1[t] = s1; r3[t] = s3; r5[t] = s5;
        __syncthreads();
        for (int off = 128; off > 0; off >>= 1) {
            if (t < off) { r1[t] += r1[t + off]; r3[t] += r3[t + off]; r5[t] += r5[t + off]; }
            __syncthreads();
        }
        if (t == 0) {
            d_S[0][b][c] = r1[0];
            d_S[1][b][c] = r3[0];
            d_S[2][b][c] = r5[0];
        }
    } else {
        const int gid = bid - 512;
        const int b = gid >> 7;
        const int n0 = (gid & 127) * 32;
        float (*Wgs)[33] = (float (*)[33])smraw;
        float* xsb = (float*)(smraw + 33792);
        const uint32_t xsb_u = smem_u32(xsb);
        const int i = t & 31, ng = t >> 5;
        const float* xb = x + (size_t)b * CC * NN;

        {
            int r = t >> 3, q = t & 7;
            cpa16(xsb_u + (r * 32 + q * 4) * 4, &xb[(size_t)r * NN + n0 + q * 4]);
            cp_commit();
        }
        #pragma unroll
        for (int it = 0; it < 32; it++) {
            int e = it * 256 + t;
            int ii = e >> 8, cc = e & 255;
            Wgs[cc][ii] = Wg[ii * CC + cc];
        }

        float acc[4] = {0.f, 0.f, 0.f, 0.f};
        for (int c = 0; c < 8; c++) {
            if (c + 1 < 8) {
                int r = t >> 3, q = t & 7;
                cpa16(xsb_u + (((c + 1) % 3) * 1024 + r * 32 + q * 4) * 4,
                      &xb[(size_t)((c + 1) * 32 + r) * NN + n0 + q * 4]);
                cp_commit();
                cp_wait1();
            } else {
                cp_wait0();
            }
            __syncthreads();
            const float* xsc = &xsb[(c % 3) * 1024];
            const int cbase = c * 32;
            #pragma unroll
            for (int cc = 0; cc < 32; cc++) {
                float w = Wgs[cbase + cc][i];
                float4 xv = *(const float4*)&xsc[cc * 32 + ng * 4];
                acc[0] += w * xv.x; acc[1] += w * xv.y; acc[2] += w * xv.z; acc[3] += w * xv.w;
            }
        }
        __half hv[4];
        #pragma unroll
        for (int j = 0; j < 4; j++) hv[j] = __float2half(acc[j]);
        *(uint2*)&d_GXT[b][i][n0 + ng * 4] = *(uint2*)hv;
    }
}

// ---------------- kernel 2: tiny V computation ----------------
__global__ void vcalc_kernel(const float* __restrict__ W1, const float* __restrict__ W2) {
    __shared__ float m[BB][3];
    const int t = threadIdx.x;
    if (t < 6) {
        int k = t % 3, b = t / 3;
        float s = 0.f;
        for (int c = 0; c < CC; c++) { float v = d_S[k][b][c]; s += v * v; }
        m[b][k] = s * (1.f / ((float)NN * (float)NN));
    }
    __syncthreads();
    if (t < BB) {
        int b = t;
        float h[16];
        #pragma unroll
        for (int i = 0; i < 16; i++)
            h[i] = W1[i * 3 + 0] * m[b][0] + W1[i * 3 + 1] * m[b][1] + W1[i * 3 + 2] * m[b][2];
        float o[3];
        #pragma unroll
        for (int j = 0; j < 3; j++) {
            float s = 0.f;
            #pragma unroll
            for (int i = 0; i < 16; i++) s += W2[j * 16 + i] * h[i];
            o[j] = s;
        }
        float mx = fmaxf(o[0], fmaxf(o[1], o[2]));
        float e0 = expf(o[0] - mx), e1 = expf(o[1] - mx), e2 = expf(o[2] - mx);
        float inv = 1.f / (e0 + e1 + e2);
        d_sqrtV[b][0] = sqrtf(e0 * inv);
        d_sqrtV[b][1] = sqrtf(e1 * inv);
        d_sqrtV[b][2] = sqrtf(e2 * inv);
    }
}

// ---------------- kernel 2b: transpose + scale + bf16 convert ----------------
__global__ void split_kernel(const float* __restrict__ x) {
    const int b = blockIdx.y;
    const int dtile = blockIdx.x % NCH;
    const int ntile = blockIdx.x / NCH;
    const int d0 = dtile * 64, n0 = ntile * 64;
    const float s = d_sqrtV[b][dtile >> 2];
    const float* src = (dtile < 4) ? (x + ((size_t)b * CC + d0) * NN)
                                   : &d_M[b][d0 - CC][0];
    __shared__ float sme[64][65];
    const int t = threadIdx.x;
    #pragma unroll
    for (int it = 0; it < 4; it++) {
        int e = it * 256 + t;
        int r = e >> 4, c4 = (e & 15) << 2;
        float4 v = *(const float4*)&src[(size_t)r * NN + n0 + c4];
        sme[r][c4] = v.x; sme[r][c4 + 1] = v.y; sme[r][c4 + 2] = v.z; sme[r][c4 + 3] = v.w;
    }
    __syncthreads();
    #pragma unroll
    for (int it = 0; it < 2; it++) {
        int e = it * 256 + t;
        int r2 = e >> 3, g = e & 7;
        __nv_bfloat16 hv[8];
        #pragma unroll
        for (int q = 0; q < 8; q++)
            hv[q] = __float2bfloat16(sme[g * 8 + q][r2] * s);
        *(uint4*)&d_Mt[b][n0 + r2][d0 + g * 8] = *(uint4*)hv;
    }
}

// ---------------- kernel 4: split-K flash, 512 threads, 16 warps ----------------
// grid (32, SPLITS, BB). warp: wr=warp>>1 rows wr*16..+15; wc=warp&1 cols wc*128..+127.
__global__ __launch_bounds__(NTHR, 1) void flash8_kernel() {
    extern __shared__ __align__(16) char sm[];
    float* smf = (float*)sm;
    const uint32_t sb = smem_u32(sm);
    const int tid = threadIdx.x, warp = tid >> 5, lane = tid & 31;
    const int i0 = blockIdx.x * TMQ;
    const int split = blockIdx.y;
    const int b = blockIdx.z;
    const int wr = warp >> 1, wc = warp & 1;

    float* pm  = smf + PM_OFF / 4;
    float* psm = smf + PSUM_OFF / 4;
    float* mr  = smf + MR_OFF / 4;
    float* lr  = smf + LR_OFF / 4;
    float* scr = smf + SCR_OFF / 4;

    if (tid < TMQ) { mr[tid] = -3.0e38f; lr[tid] = 0.f; }
    __syncthreads();

    const int nl = (lane & 7) | ((lane & 16) >> 1);
    const int kh = (lane >> 3) & 1;
    const int ra = wr * 16 + (lane >> 2);   // row a; row b = ra + 8

    float yacc[4][4];
    #pragma unroll
    for (int ng = 0; ng < 4; ng++)
        #pragma unroll
        for (int q = 0; q < 4; q++) yacc[ng][q] = 0.f;

    const __nv_bfloat16* Mb = &d_Mt[b][0][0];

    for (int jt = 0; jt < NJT; jt++) {
        const int j0 = split * KEYS + jt * TNK;

        // prologue: chunk 0 (stage 0) + VT tile
        {
            uint32_t qb = sb;
            #pragma unroll
            for (int it = 0; it < 2; it++) {
                int e = it * NTHR + tid, r = e >> 3, g = e & 7;
                cpa16(qb + sw128(r * 128 + g * 16), Mb + (size_t)(i0 + r) * DD + g * 8);
            }
            #pragma unroll
            for (int it = 0; it < 4; it++) {
                int e = it * NTHR + tid, r = e >> 3, g = e & 7;
                cpa16(qb + KOFF + sw128(r * 128 + g * 16), Mb + (size_t)(j0 + r) * DD + g * 8);
            }
            #pragma unroll
            for (int it = 0; it < 2; it++) {
                int e = it * NTHR + tid, r = e >> 5, g = e & 31;
                cpa16(sb + VTS_OFF + r * VT_PITCH + g * 16, &d_GXT[b][r][j0 + g * 8]);
            }
            cp_commit();
        }

        float acc[16][4];
        #pragma unroll
        for (int t = 0; t < 16; t++)
            #pragma unroll
            for (int q = 0; q < 4; q++) acc[t][q] = 0.f;

        for (int c = 0; c < NCH; c++) {
            cp_wait0();
            __syncthreads();
            if (c + 1 < NCH) {
                uint32_t qb = sb + ((c + 1) & 1) * STAGE_BYTES;
                const int d0 = (c + 1) * KC;
                #pragma unroll
                for (int it = 0; it < 2; it++) {
                    int e = it * NTHR + tid, r = e >> 3, g = e & 7;
                    cpa16(qb + sw128(r * 128 + g * 16), Mb + (size_t)(i0 + r) * DD + d0 + g * 8);
                }
                #pragma unroll
                for (int it = 0; it < 4; it++) {
                    int e = it * NTHR + tid, r = e >> 3, g = e & 7;
                    cpa16(qb + KOFF + sw128(r * 128 + g * 16), Mb + (size_t)(j0 + r) * DD + d0 + g * 8);
                }
                cp_commit();
            }
            const uint32_t qb = sb + (c & 1) * STAGE_BYTES;
            const uint32_t kb = qb + KOFF;
            #pragma unroll
            for (int k16 = 0; k16 < 4; k16++) {
                uint32_t afr[4];
                ldsm4(afr, qb + sw128((wr * 16 + (lane & 15)) * 128 + k16 * 32 + (lane >> 4) * 16));
                #pragma unroll
                for (int nt = 0; nt < 8; nt++) {
                    uint32_t bfr[4];
                    ldsm4(bfr, kb + sw128((wc * 128 + nt * 16 + nl) * 128 + k16 * 32 + kh * 16));
                    mma_bf16(acc[2 * nt],     afr, bfr[0], bfr[1]);
                    mma_bf16(acc[2 * nt + 1], afr, bfr[2], bfr[3]);
                }
            }
        }

        // ---- row max (rows span 2 warps: wc=0,1) ----
        float ma = -3.0e38f, mb2 = -3.0e38f;
        #pragma unroll
        for (int t = 0; t < 16; t++) {
            ma  = fmaxf(ma,  fmaxf(acc[t][0], acc[t][1]));
            mb2 = fmaxf(mb2, fmaxf(acc[t][2], acc[t][3]));
        }
        ma = qredmax(ma); mb2 = qredmax(mb2);
        if ((lane & 3) == 0) {
            pm[wc * 128 + ra]     = ma;
            pm[wc * 128 + ra + 8] = mb2;
        }
        __syncthreads();
        if (tid < TMQ) {
            float mo = mr[tid];
            float mn = fmaxf(mo, fmaxf(pm[tid], pm[128 + tid]));
            scr[tid] = __expf(mo - mn);
            mr[tid] = mn;
        }
        __syncthreads();

        // ---- fused exp + PV (P stays in registers as A fragments) ----
        float mna = mr[ra], mnb = mr[ra + 8];
        float sca = scr[ra], scb = scr[ra + 8];
        #pragma unroll
        for (int ng = 0; ng < 4; ng++) {
            yacc[ng][0] *= sca; yacc[ng][1] *= sca;
            yacc[ng][2] *= scb; yacc[ng][3] *= scb;
        }
        float sa = 0.f, sb2 = 0.f;
        #pragma unroll
        for (int t = 0; t < 8; t++) {
            uint32_t bfr0[4], bfr1[4];
            ldsm4(bfr0, sb + VTS_OFF + nl * VT_PITCH        + wc * 256 + t * 32 + kh * 16);
            ldsm4(bfr1, sb + VTS_OFF + (16 + nl) * VT_PITCH + wc * 256 + t * 32 + kh * 16);
            float e0 = __expf(acc[2 * t][0] - mna);
            float e1 = __expf(acc[2 * t][1] - mna);
            float e2 = __expf(acc[2 * t][2] - mnb);
            float e3 = __expf(acc[2 * t][3] - mnb);
            float e4 = __expf(acc[2 * t + 1][0] - mna);
            float e5 = __expf(acc[2 * t + 1][1] - mna);
            float e6 = __expf(acc[2 * t + 1][2] - mnb);
            float e7 = __expf(acc[2 * t + 1][3] - mnb);
            sa  += e0 + e1 + e4 + e5;
            sb2 += e2 + e3 + e6 + e7;
            uint32_t a[4];
            __half2 h;
            h = __floats2half2_rn(e0, e1); a[0] = *(uint32_t*)&h;
            h = __floats2half2_rn(e2, e3); a[1] = *(uint32_t*)&h;
            h = __floats2half2_rn(e4, e5); a[2] = *(uint32_t*)&h;
            h = __floats2half2_rn(e6, e7); a[3] = *(uint32_t*)&h;
            mma_f16(yacc[0], a, bfr0[0], bfr0[1]);
            mma_f16(yacc[1], a, bfr0[2], bfr0[3]);
            mma_f16(yacc[2], a, bfr1[0], bfr1[1]);
            mma_f16(yacc[3], a, bfr1[2], bfr1[3]);
        }
        sa = qredsum(sa); sb2 = qredsum(sb2);
        if ((lane & 3) == 0) {
            psm[wc * 128 + ra]     = sa;
            psm[wc * 128 + ra + 8] = sb2;
        }
        __syncthreads();
        if (tid < TMQ) lr[tid] = lr[tid] * scr[tid] + psm[tid] + psm[128 + tid];
    }

    // ---- write split partials: combine wc halves, store O, m, l ----
    __syncthreads();
    float* yp = smf;   // [128][32], aliases stage0
    if (wc == 0) {
        #pragma unroll
        for (int ng = 0; ng < 4; ng++)
            #pragma unroll
            for (int q = 0; q < 4; q++) {
                int row = wr * 16 + (lane >> 2) + ((q & 2) ? 8 : 0);
                int col = ng * 8 + (lane & 3) * 2 + (q & 1);
                yp[row * 32 + col] = yacc[ng][q];
            }
    }
    __syncthreads();
    const int sidx = b * SPLITS + split;
    if (wc == 1) {
        #pragma unroll
        for (int ng = 0; ng < 4; ng++)
            #pragma unroll
            for (int q = 0; q < 4; q++) {
                int row = wr * 16 + (lane >> 2) + ((q & 2) ? 8 : 0);
                int col = ng * 8 + (lane & 3) * 2 + (q & 1);
                d_part[sidx][i0 + row][col] = yp[row * 32 + col] + yacc[ng][q];
            }
    }
    if (tid < TMQ) d_ml[sidx][i0 + tid] = make_float2(mr[tid], lr[tid]);
}

// ---------------- kernel 5: split combine + Ww conv + residual ----------------
__global__ void combine_kernel(const float* __restrict__ x,
                               const float* __restrict__ Ww,
                               float* __restrict__ out) {
    const int b = blockIdx.y;
    const int r0 = blockIdx.x * 64;
    __shared__ float ysT[32][68];
    __shared__ float Ws[CC * IN];
    __shared__ float wA[64], wB[64];
    const int t = threadIdx.x;
    if (t < 64) {
        float2 ml0 = d_ml[b * SPLITS + 0][r0 + t];
        float2 ml1 = d_ml[b * SPLITS + 1][r0 + t];
        float m = fmaxf(ml0.x, ml1.x);
        float w0 = __expf(ml0.x - m), w1 = __expf(ml1.x - m);
        float inv = 1.f / (ml0.y * w0 + ml1.y * w1);
        wA[t] = w0 * inv; wB[t] = w1 * inv;
    }
    #pragma unroll
    for (int it = 0; it < 32; it++) Ws[it * 256 + t] = Ww[it * 256 + t];
    __syncthreads();
    for (int idx = t; idx < 64 * IN; idx += 256) {
        int rl = idx >> 5, col = idx & 31;
        ysT[col][rl] = d_part[b * SPLITS + 0][r0 + rl][col] * wA[rl]
                     + d_part[b * SPLITS + 1][r0 + rl][col] * wB[rl];
    }
    __syncthreads();

    const int r = t & 63;
    const int cg = t >> 6;
    float yreg[IN];
    #pragma unroll
    for (int i = 0; i < IN; i++) yreg[i] = ysT[i][r];
    const float* xb = x + (size_t)b * CC * NN;
    float* ob = out + (size_t)b * CC * NN;
    #pragma unroll 4
    for (int k = 0; k < 64; k++) {
        int c = cg * 64 + k;
        float s = 0.f;
        #pragma unroll
        for (int q = 0; q < 8; q++) {
            float4 w4 = *(const float4*)&Ws[c * 32 + q * 4];
            s += w4.x * yreg[q * 4] + w4.y * yreg[q * 4 + 1] + w4.z * yreg[q * 4 + 2] + w4.w * yreg[q * 4 + 3];
        }
        ob[(size_t)c * NN + r0 + r] = s + xb[(size_t)c * NN + r0 + r];
    }
}

extern "C" void kernel_launch(void* const* d_in, const int* in_sizes, int n_in,
                              void* d_out, int out_size) {
    const float* x  = (const float*)d_in[0];
    const float* Wg = (const float*)d_in[1];
    const float* Ww = (const float*)d_in[2];
    const float* W1 = (const float*)d_in[3];
    const float* W2 = (const float*)d_in[4];
    float* out = (float*)d_out;

    static int configured = 0;
    if (!configured) {
        cudaFuncSetAttribute(flash8_kernel, cudaFuncAttributeMaxDynamicSharedMemorySize, FLASH_SMEM);
        configured = 1;
    }

    prep_kernel<<<768, 256>>>(x, Wg);
    vcalc_kernel<<<1, 64>>>(W1, W2);
    split_kernel<<<dim3(NCH * (NN / 64), BB), 256>>>(x);
    flash8_kernel<<<dim3(NN / TMQ, SPLITS, BB), NTHR, FLASH_SMEM>>>();
    combine_kernel<<<dim3(NN / 64, BB), 256>>>(x, Ww, out);
}

// round 13
// speedup vs baseline: 1.1975x; 1.1975x over previous
#include <cuda_runtime.h>
#include <cuda_bf16.h>
#include <cuda_fp16.h>
#include <cstdint>

// Problem constants
#define BB 2
#define CC 256
#define NN 4096          // 64*64
#define DD 768           // 3*CC
#define IN 32            // inter

// Flash tiling (R7/R10-proven geometry)
#define TMQ 128          // q rows per block
#define TNK 256          // keys per j-tile
#define KC 64            // feature chunk (=128B bf16 row)
#define NCH (DD / KC)    // 12
#define SPLITS 2
#define NSPL (SPLITS * 2)    // splits x col-halves
#define KEYS (NN / SPLITS)   // 2048
#define NJT (KEYS / TNK)     // 8

// SMEM layout (bytes) for flash
#define KOFF   16384
#define STAGE_BYTES 49152      // Q 16K + K 32K
#define VTS_OFF 98304          // 2 x fp16 VT [32][272] (pitch 544B)
#define VT_PITCH 544
#define VT_STAGE 17408
#define FLASH_SMEM 133120

// Scratch (static device globals; no allocation)
__device__ float d_M[BB][2 * CC][NN];                     // pooled variants 3,5 (fp32)
__device__ __align__(16) __nv_bfloat16 d_Mt[BB][NN][DD];  // token-major, scaled, bf16
__device__ __align__(16) __half d_GXT[BB][IN][NN];        // g_x as [b][i][n], fp16
__device__ float d_S[3][BB][CC];
__device__ float d_sqrtV[BB][3];
__device__ float d_part[BB * NSPL][NN][IN];               // partial O (unnormalized)
__device__ float2 d_ml[BB * NSPL][NN];                    // partial (m, l)

// ---------------- helpers ----------------
__device__ __forceinline__ uint32_t smem_u32(const void* p) {
    uint32_t a;
    asm("{ .reg .u64 t; cvta.to.shared.u64 t, %1; cvt.u32.u64 %0, t; }" : "=r"(a) : "l"(p));
    return a;
}
__device__ __forceinline__ uint32_t sw128(uint32_t bo) { return bo ^ ((bo >> 3) & 0x70); }

__device__ __forceinline__ void cpa16(uint32_t dst, const void* src) {
    asm volatile("cp.async.cg.shared.global [%0], [%1], 16;" :: "r"(dst), "l"(src));
}
__device__ __forceinline__ void cp_commit() { asm volatile("cp.async.commit_group;"); }
__device__ __forceinline__ void cp_wait0() { asm volatile("cp.async.wait_group 0;"); }
__device__ __forceinline__ void cp_wait1() { asm volatile("cp.async.wait_group 1;"); }

__device__ __forceinline__ void ldsm4(uint32_t* r, uint32_t addr) {
    asm volatile("ldmatrix.sync.aligned.m8n8.x4.shared.b16 {%0,%1,%2,%3}, [%4];"
                 : "=r"(r[0]), "=r"(r[1]), "=r"(r[2]), "=r"(r[3]) : "r"(addr));
}
__device__ __forceinline__ void mma_bf16(float* c, const uint32_t* a, uint32_t b0, uint32_t b1) {
    asm volatile("mma.sync.aligned.m16n8k16.row.col.f32.bf16.bf16.f32 "
                 "{%0,%1,%2,%3},{%4,%5,%6,%7},{%8,%9},{%0,%1,%2,%3};"
                 : "+f"(c[0]), "+f"(c[1]), "+f"(c[2]), "+f"(c[3])
                 : "r"(a[0]), "r"(a[1]), "r"(a[2]), "r"(a[3]), "r"(b0), "r"(b1));
}
__device__ __forceinline__ void mma_f16(float* c, const uint32_t* a, uint32_t b0, uint32_t b1) {
    asm volatile("mma.sync.aligned.m16n8k16.row.col.f32.f16.f16.f32 "
                 "{%0,%1,%2,%3},{%4,%5,%6,%7},{%8,%9},{%0,%1,%2,%3};"
                 : "+f"(c[0]), "+f"(c[1]), "+f"(c[2]), "+f"(c[3])
                 : "r"(a[0]), "r"(a[1]), "r"(a[2]), "r"(a[3]), "r"(b0), "r"(b1));
}
__device__ __forceinline__ float qredmax(float v) {
    v = fmaxf(v, __shfl_xor_sync(0xffffffffu, v, 1));
    v = fmaxf(v, __shfl_xor_sync(0xffffffffu, v, 2));
    return v;
}
__device__ __forceinline__ float qredsum(float v) {
    v += __shfl_xor_sync(0xffffffffu, v, 1);
    v += __shfl_xor_sync(0xffffffffu, v, 2);
    return v;
}

// ---------------- kernel 1: MERGED pool + gx (R10-proven) ----------------
__global__ __launch_bounds__(256) void prep_kernel(const float* __restrict__ x,
                                                   const float* __restrict__ Wg) {
    __shared__ __align__(16) char smraw[49152];
    const int bid = blockIdx.x;
    const int t = threadIdx.x;

    if (bid < 512) {
        const int c = bid & 255, b = bid >> 8;
        const float* xp = x + ((size_t)(b * CC + c)) * NN;
        float (*xs)[64] = (float (*)[64])smraw;
        float (*h3)[64] = (float (*)[64])(smraw + 16384);
        float (*h5)[64] = (float (*)[64])(smraw + 32768);

        for (int p = t; p < NN; p += 256) xs[p >> 6][p & 63] = xp[p];
        __syncthreads();
        for (int p = t; p < NN; p += 256) {
            int h = p >> 6, w = p & 63;
            float c0 = xs[h][w];
            float l1 = (w > 0)  ? xs[h][w - 1] : 0.f;
            float r1 = (w < 63) ? xs[h][w + 1] : 0.f;
            float l2 = (w > 1)  ? xs[h][w - 2] : 0.f;
            float r2 = (w < 62) ? xs[h][w + 2] : 0.f;
            h3[h][w] = l1 + c0 + r1;
            h5[h][w] = l2 + l1 + c0 + r1 + r2;
        }
        __syncthreads();
        float s1 = 0.f, s3 = 0.f, s5 = 0.f;
        float* M3 = &d_M[b][c][0];
        float* M5 = &d_M[b][CC + c][0];
        for (int p = t; p < NN; p += 256) {
            int h = p >> 6, w = p & 63;
            float v0 = xs[h][w];
            float u1 = (h > 0)  ? h3[h - 1][w] : 0.f;
            float dn1 = (h < 63) ? h3[h + 1][w] : 0.f;
            float u2 = (h > 1)  ? h5[h - 2][w] : 0.f;
            float dn2 = (h < 62) ? h5[h + 2][w] : 0.f;
            float u1b = (h > 0)  ? h5[h - 1][w] : 0.f;
            float dn1b = (h < 63) ? h5[h + 1][w] : 0.f;
            float p3 = (u1 + h3[h][w] + dn1) * (1.f / 9.f);
            float p5 = (u2 + u1b + h5[h][w] + dn1b + dn2) * (1.f / 25.f);
            M3[p] = p3; M5[p] = p5;
            s1 += v0; s3 += p3; s5 += p5;
        }
        __syncthreads();
        float* r1 = (float*)smraw;
        float* r3 = (float*)(smraw + 16384);
        float* r5 = (float*)(smraw + 32768);
        r1[t] = s1; r3[t] = s3; r5[t] = s5;
        __syncthreads();
        for (int off = 128; off > 0; off >>= 1) {
            if (t < off) { r1[t] += r1[t + off]; r3[t] += r3[t + off]; r5[t] += r5[t + off]; }
            __syncthreads();
        }
        if (t == 0) {
            d_S[0][b][c] = r1[0];
            d_S[1][b][c] = r3[0];
            d_S[2][b][c] = r5[0];
        }
    } else {
        const int gid = bid - 512;
        const int b = gid >> 7;
        const int n0 = (gid & 127) * 32;
        float (*Wgs)[33] = (float (*)[33])smraw;
        float* xsb = (float*)(smraw + 33792);
        const uint32_t xsb_u = smem_u32(xsb);
        const int i = t & 31, ng = t >> 5;
        const float* xb = x + (size_t)b * CC * NN;

        {
            int r = t >> 3, q = t & 7;
            cpa16(xsb_u + (r * 32 + q * 4) * 4, &xb[(size_t)r * NN + n0 + q * 4]);
            cp_commit();
        }
        #pragma unroll
        for (int it = 0; it < 32; it++) {
            int e = it * 256 + t;
            int ii = e >> 8, cc = e & 255;
            Wgs[cc][ii] = Wg[ii * CC + cc];
        }

        float acc[4] = {0.f, 0.f, 0.f, 0.f};
        for (int c = 0; c < 8; c++) {
            if (c + 1 < 8) {
                int r = t >> 3, q = t & 7;
                cpa16(xsb_u + (((c + 1) % 3) * 1024 + r * 32 + q * 4) * 4,
                      &xb[(size_t)((c + 1) * 32 + r) * NN + n0 + q * 4]);
                cp_commit();
                cp_wait1();
            } else {
                cp_wait0();
            }
            __syncthreads();
            const float* xsc = &xsb[(c % 3) * 1024];
            const int cbase = c * 32;
            #pragma unroll
            for (int cc = 0; cc < 32; cc++) {
                float w = Wgs[cbase + cc][i];
                float4 xv = *(const float4*)&xsc[cc * 32 + ng * 4];
                acc[0] += w * xv.x; acc[1] += w * xv.y; acc[2] += w * xv.z; acc[3] += w * xv.w;
            }
        }
        __half hv[4];
        #pragma unroll
        for (int j = 0; j < 4; j++) hv[j] = __float2half(acc[j]);
        *(uint2*)&d_GXT[b][i][n0 + ng * 4] = *(uint2*)hv;
    }
}

// ---------------- kernel 2: tiny V computation ----------------
__global__ void vcalc_kernel(const float* __restrict__ W1, const float* __restrict__ W2) {
    __shared__ float m[BB][3];
    const int t = threadIdx.x;
    if (t < 6) {
        int k = t % 3, b = t / 3;
        float s = 0.f;
        for (int c = 0; c < CC; c++) { float v = d_S[k][b][c]; s += v * v; }
        m[b][k] = s * (1.f / ((float)NN * (float)NN));
    }
    __syncthreads();
    if (t < BB) {
        int b = t;
        float h[16];
        #pragma unroll
        for (int i = 0; i < 16; i++)
            h[i] = W1[i * 3 + 0] * m[b][0] + W1[i * 3 + 1] * m[b][1] + W1[i * 3 + 2] * m[b][2];
        float o[3];
        #pragma unroll
        for (int j = 0; j < 3; j++) {
            float s = 0.f;
            #pragma unroll
            for (int i = 0; i < 16; i++) s += W2[j * 16 + i] * h[i];
            o[j] = s;
        }
        float mx = fmaxf(o[0], fmaxf(o[1], o[2]));
        float e0 = expf(o[0] - mx), e1 = expf(o[1] - mx), e2 = expf(o[2] - mx);
        float inv = 1.f / (e0 + e1 + e2);
        d_sqrtV[b][0] = sqrtf(e0 * inv);
        d_sqrtV[b][1] = sqrtf(e1 * inv);
        d_sqrtV[b][2] = sqrtf(e2 * inv);
    }
}

// ---------------- kernel 2b: transpose + scale + bf16 convert ----------------
__global__ void split_kernel(const float* __restrict__ x) {
    const int b = blockIdx.y;
    const int dtile = blockIdx.x % NCH;
    const int ntile = blockIdx.x / NCH;
    const int d0 = dtile * 64, n0 = ntile * 64;
    const float s = d_sqrtV[b][dtile >> 2];
    const float* src = (dtile < 4) ? (x + ((size_t)b * CC + d0) * NN)
                                   : &d_M[b][d0 - CC][0];
    __shared__ float sme[64][65];
    const int t = threadIdx.x;
    #pragma unroll
    for (int it = 0; it < 4; it++) {
        int e = it * 256 + t;
        int r = e >> 4, c4 = (e & 15) << 2;
        float4 v = *(const float4*)&src[(size_t)r * NN + n0 + c4];
        sme[r][c4] = v.x; sme[r][c4 + 1] = v.y; sme[r][c4 + 2] = v.z; sme[r][c4 + 3] = v.w;
    }
    __syncthreads();
    #pragma unroll
    for (int it = 0; it < 2; it++) {
        int e = it * 256 + t;
        int r2 = e >> 3, g = e & 7;
        __nv_bfloat16 hv[8];
        #pragma unroll
        for (int q = 0; q < 8; q++)
            hv[q] = __float2bfloat16(sme[g * 8 + q][r2] * s);
        *(uint4*)&d_Mt[b][n0 + r2][d0 + g * 8] = *(uint4*)hv;
    }
}

// ---------------- kernel 4: split-K flash, barrier-free warp-local softmax ----------------
// grid (32, SPLITS, BB), 256 threads (8 warps).
// warp: wr=warp>>1 rows wr*32..+31; wc=warp&1 cols wc*128..+127 (own (m,l,O) partial).
__global__ __launch_bounds__(256, 1) void flash9_kernel() {
    extern __shared__ __align__(16) char sm[];
    const uint32_t sb = smem_u32(sm);
    const int tid = threadIdx.x, warp = tid >> 5, lane = tid & 31;
    const int i0 = blockIdx.x * TMQ;
    const int split = blockIdx.y;
    const int b = blockIdx.z;
    const int wr = warp >> 1, wc = warp & 1;

    const int nl = (lane & 7) | ((lane & 16) >> 1);
    const int kh = (lane >> 3) & 1;

    float m_[2][2], l_[2][2];
    #pragma unroll
    for (int rt = 0; rt < 2; rt++) { m_[rt][0] = -3.0e38f; m_[rt][1] = -3.0e38f; l_[rt][0] = 0.f; l_[rt][1] = 0.f; }

    float yacc[2][4][4];
    #pragma unroll
    for (int rt = 0; rt < 2; rt++)
        #pragma unroll
        for (int ng = 0; ng < 4; ng++)
            #pragma unroll
            for (int q = 0; q < 4; q++) yacc[rt][ng][q] = 0.f;

    const __nv_bfloat16* Mb = &d_Mt[b][0][0];

    // prologue for tile jt: chunk 0 into stage 0 + VT into buffer jt&1
    auto prologue = [&](int jt) {
        const int j0 = split * KEYS + jt * TNK;
        #pragma unroll
        for (int it = 0; it < 4; it++) {
            int e = it * 256 + tid, r = e >> 3, g = e & 7;
            cpa16(sb + sw128(r * 128 + g * 16), Mb + (size_t)(i0 + r) * DD + g * 8);
        }
        #pragma unroll
        for (int it = 0; it < 8; it++) {
            int e = it * 256 + tid, r = e >> 3, g = e & 7;
            cpa16(sb + KOFF + sw128(r * 128 + g * 16), Mb + (size_t)(j0 + r) * DD + g * 8);
        }
        const uint32_t vb = sb + VTS_OFF + (jt & 1) * VT_STAGE;
        #pragma unroll
        for (int it = 0; it < 4; it++) {
            int e = it * 256 + tid, r = e >> 5, g = e & 31;
            cpa16(vb + r * VT_PITCH + g * 16, &d_GXT[b][r][j0 + g * 8]);
        }
        cp_commit();
    };
    prologue(0);

    for (int jt = 0; jt < NJT; jt++) {
        const int j0 = split * KEYS + jt * TNK;

        float acc[2][16][4];
        #pragma unroll
        for (int rt = 0; rt < 2; rt++)
            #pragma unroll
            for (int t = 0; t < 16; t++)
                #pragma unroll
                for (int q = 0; q < 4; q++) acc[rt][t][q] = 0.f;

        for (int c = 0; c < NCH; c++) {
            cp_wait0();
            __syncthreads();
            if (c + 1 < NCH) {
                uint32_t qb = sb + ((c + 1) & 1) * STAGE_BYTES;
                const int d0 = (c + 1) * KC;
                #pragma unroll
                for (int it = 0; it < 4; it++) {
                    int e = it * 256 + tid, r = e >> 3, g = e & 7;
                    cpa16(qb + sw128(r * 128 + g * 16), Mb + (size_t)(i0 + r) * DD + d0 + g * 8);
                }
                #pragma unroll
                for (int it = 0; it < 8; it++) {
                    int e = it * 256 + tid, r = e >> 3, g = e & 7;
                    cpa16(qb + KOFF + sw128(r * 128 + g * 16), Mb + (size_t)(j0 + r) * DD + d0 + g * 8);
                }
                cp_commit();
            }
            const uint32_t qb = sb + (c & 1) * STAGE_BYTES;
            const uint32_t kb = qb + KOFF;
            #pragma unroll
            for (int k16 = 0; k16 < 4; k16++) {
                uint32_t afr[2][4];
                ldsm4(afr[0], qb + sw128((wr * 32 + (lane & 15)) * 128 + k16 * 32 + (lane >> 4) * 16));
                ldsm4(afr[1], qb + sw128((wr * 32 + 16 + (lane & 15)) * 128 + k16 * 32 + (lane >> 4) * 16));
                #pragma unroll
                for (int nt = 0; nt < 8; nt++) {
                    uint32_t bfr[4];
                    ldsm4(bfr, kb + sw128((wc * 128 + nt * 16 + nl) * 128 + k16 * 32 + kh * 16));
                    mma_bf16(acc[0][2 * nt],     afr[0], bfr[0], bfr[1]);
                    mma_bf16(acc[0][2 * nt + 1], afr[0], bfr[2], bfr[3]);
                    mma_bf16(acc[1][2 * nt],     afr[1], bfr[0], bfr[1]);
                    mma_bf16(acc[1][2 * nt + 1], afr[1], bfr[2], bfr[3]);
                }
            }
        }

        // hoist next tile's chunk-0 + VT loads over the serial phase
        if (jt + 1 < NJT) prologue(jt + 1);

        // ---- warp-local online softmax (barrier-free) ----
        float mna[2], mnb[2];
        #pragma unroll
        for (int rt = 0; rt < 2; rt++) {
            float ma = -3.0e38f, mb2 = -3.0e38f;
            #pragma unroll
            for (int t = 0; t < 16; t++) {
                ma  = fmaxf(ma,  fmaxf(acc[rt][t][0], acc[rt][t][1]));
                mb2 = fmaxf(mb2, fmaxf(acc[rt][t][2], acc[rt][t][3]));
            }
            ma = qredmax(ma); mb2 = qredmax(mb2);
            float na = fmaxf(m_[rt][0], ma), nb = fmaxf(m_[rt][1], mb2);
            float sca = __expf(m_[rt][0] - na), scb = __expf(m_[rt][1] - nb);
            m_[rt][0] = na; m_[rt][1] = nb;
            l_[rt][0] *= sca; l_[rt][1] *= scb;
            mna[rt] = na; mnb[rt] = nb;
            #pragma unroll
            for (int ng = 0; ng < 4; ng++) {
                yacc[rt][ng][0] *= sca; yacc[rt][ng][1] *= sca;
                yacc[rt][ng][2] *= scb; yacc[rt][ng][3] *= scb;
            }
        }

        // ---- fused exp + PV (P in registers; VT double-buffered) ----
        const uint32_t vtb = sb + VTS_OFF + (jt & 1) * VT_STAGE;
        float sa[2] = {0.f, 0.f}, sb2[2] = {0.f, 0.f};
        #pragma unroll
        for (int t = 0; t < 8; t++) {
            uint32_t bfr0[4], bfr1[4];
            ldsm4(bfr0, vtb + nl * VT_PITCH        + wc * 256 + t * 32 + kh * 16);
            ldsm4(bfr1, vtb + (16 + nl) * VT_PITCH + wc * 256 + t * 32 + kh * 16);
            #pragma unroll
            for (int rt = 0; rt < 2; rt++) {
                float e0 = __expf(acc[rt][2 * t][0] - mna[rt]);
                float e1 = __expf(acc[rt][2 * t][1] - mna[rt]);
                float e2 = __expf(acc[rt][2 * t][2] - mnb[rt]);
                float e3 = __expf(acc[rt][2 * t][3] - mnb[rt]);
                float e4 = __expf(acc[rt][2 * t + 1][0] - mna[rt]);
                float e5 = __expf(acc[rt][2 * t + 1][1] - mna[rt]);
                float e6 = __expf(acc[rt][2 * t + 1][2] - mnb[rt]);
                float e7 = __expf(acc[rt][2 * t + 1][3] - mnb[rt]);
                sa[rt]  += e0 + e1 + e4 + e5;
                sb2[rt] += e2 + e3 + e6 + e7;
                uint32_t a[4];
                __half2 h;
                h = __floats2half2_rn(e0, e1); a[0] = *(uint32_t*)&h;
                h = __floats2half2_rn(e2, e3); a[1] = *(uint32_t*)&h;
                h = __floats2half2_rn(e4, e5); a[2] = *(uint32_t*)&h;
                h = __floats2half2_rn(e6, e7); a[3] = *(uint32_t*)&h;
                mma_f16(yacc[rt][0], a, bfr0[0], bfr0[1]);
                mma_f16(yacc[rt][1], a, bfr0[2], bfr0[3]);
                mma_f16(yacc[rt][2], a, bfr1[0], bfr1[1]);
                mma_f16(yacc[rt][3], a, bfr1[2], bfr1[3]);
            }
        }
        #pragma unroll
        for (int rt = 0; rt < 2; rt++) {
            l_[rt][0] += qredsum(sa[rt]);
            l_[rt][1] += qredsum(sb2[rt]);
        }
    }

    // ---- epilogue: straight register->global partial store (no barriers) ----
    const int sidx = (b * SPLITS + split) * 2 + wc;
    #pragma unroll
    for (int rt = 0; rt < 2; rt++) {
        int rowa = i0 + wr * 32 + rt * 16 + (lane >> 2);
        #pragma unroll
        for (int ng = 0; ng < 4; ng++) {
            int col = ng * 8 + (lane & 3) * 2;
            *(float2*)&d_part[sidx][rowa][col]     = make_float2(yacc[rt][ng][0], yacc[rt][ng][1]);
            *(float2*)&d_part[sidx][rowa + 8][col] = make_float2(yacc[rt][ng][2], yacc[rt][ng][3]);
        }
        if ((lane & 3) == 0) {
            d_ml[sidx][rowa]     = make_float2(m_[rt][0], l_[rt][0]);
            d_ml[sidx][rowa + 8] = make_float2(m_[rt][1], l_[rt][1]);
        }
    }
}

// ---------------- kernel 5: 4-way partial combine + Ww conv + residual ----------------
__global__ void combine_kernel(const float* __restrict__ x,
                               const float* __restrict__ Ww,
                               float* __restrict__ out) {
    const int b = blockIdx.y;
    const int r0 = blockIdx.x * 64;
    __shared__ float ysT[32][68];
    __shared__ float Ws[CC * IN];
    __shared__ float wS[NSPL][64];
    const int t = threadIdx.x;
    if (t < 64) {
        float2 ml[NSPL];
        float m = -3.0e38f;
        #pragma unroll
        for (int s = 0; s < NSPL; s++) {
            ml[s] = d_ml[b * NSPL + s][r0 + t];
            m = fmaxf(m, ml[s].x);
        }
        float lsum = 0.f, w[NSPL];
        #pragma unroll
        for (int s = 0; s < NSPL; s++) {
            w[s] = __expf(ml[s].x - m);
            lsum += ml[s].y * w[s];
        }
        float inv = 1.f / lsum;
        #pragma unroll
        for (int s = 0; s < NSPL; s++) wS[s][t] = w[s] * inv;
    }
    #pragma unroll
    for (int it = 0; it < 32; it++) Ws[it * 256 + t] = Ww[it * 256 + t];
    __syncthreads();
    for (int idx = t; idx < 64 * IN; idx += 256) {
        int rl = idx >> 5, col = idx & 31;
        float acc = 0.f;
        #pragma unroll
        for (int s = 0; s < NSPL; s++)
            acc += d_part[b * NSPL + s][r0 + rl][col] * wS[s][rl];
        ysT[col][rl] = acc;
    }
    __syncthreads();

    const int r = t & 63;
    const int cg = t >> 6;
    float yreg[IN];
    #pragma unroll
    for (int i = 0; i < IN; i++) yreg[i] = ysT[i][r];
    const float* xb = x + (size_t)b * CC * NN;
    float* ob = out + (size_t)b * CC * NN;
    #pragma unroll 4
    for (int k = 0; k < 64; k++) {
        int c = cg * 64 + k;
        float s = 0.f;
        #pragma unroll
        for (int q = 0; q < 8; q++) {
            float4 w4 = *(const float4*)&Ws[c * 32 + q * 4];
            s += w4.x * yreg[q * 4] + w4.y * yreg[q * 4 + 1] + w4.z * yreg[q * 4 + 2] + w4.w * yreg[q * 4 + 3];
        }
        ob[(size_t)c * NN + r0 + r] = s + xb[(size_t)c * NN + r0 + r];
    }
}

extern "C" void kernel_launch(void* const* d_in, const int* in_sizes, int n_in,
                              void* d_out, int out_size) {
    const float* x  = (const float*)d_in[0];
    const float* Wg = (const float*)d_in[1];
    const float* Ww = (const float*)d_in[2];
    const float* W1 = (const float*)d_in[3];
    const float* W2 = (const float*)d_in[4];
    float* out = (float*)d_out;

    static int configured = 0;
    if (!configured) {
        cudaFuncSetAttribute(flash9_kernel, cudaFuncAttributeMaxDynamicSharedMemorySize, FLASH_SMEM);
        configured = 1;
    }

    prep_kernel<<<768, 256>>>(x, Wg);
    vcalc_kernel<<<1, 64>>>(W1, W2);
    split_kernel<<<dim3(NCH * (NN / 64), BB), 256>>>(x);
    flash9_kernel<<<dim3(NN / TMQ, SPLITS, BB), 256, FLASH_SMEM>>>();
    combine_kernel<<<dim3(NN / 64, BB), 256>>>(x, Ww, out);
}